// round 11
// baseline (speedup 1.0000x reference)
#include <cuda_runtime.h>
#include <cuda_fp16.h>
#include <cstdint>

// out[b] = x_b^T Q x_b, B=131072, F=512, fp32, Q upper-triangular (incl diag).
// fp16 HMMA. CTA tile 64x128, 256 threads, 8 warps = wk(2) x wm(2) x wn(2),
// warp tile 32x64 over half the k-steps. Pre-baked swizzled B tiles streamed
// via cp.async.bulk into a 3-stage mbarrier ring (R9-proven sync structure).
// ~113KB smem => 2 CTAs/SM for cross-CTA latency hiding. Epilogue reads x
// (fp16) from the A smem tile => x hits DRAM exactly once.

#define F_DIM 512
#define BM 64
#define BN 128
#define KC 64
#define NTHREADS 256
#define NIT 20
#define NSTAGE 3
#define TILE_B 16384      // bytes per B tile (128 rows x 128B)

// pre-baked B tiles: [NIT][128 rows][64 halfs], ldmatrix-swizzled
__device__ __half g_Btiles[NIT * 8192];

__device__ __constant__ int TN[NIT] = {0,0,1,1,1,1,2,2,2,2,2,2,3,3,3,3,3,3,3,3};
__device__ __constant__ int TC[NIT] = {0,1,0,1,2,3,0,1,2,3,4,5,0,1,2,3,4,5,6,7};

// smem layout
#define SM_A     0                          // 64 rows x 1024B = 64KB
#define SM_B     65536                      // 3 stages x 16KB = 48KB
#define SM_MBAR  (SM_B + NSTAGE * TILE_B)
#define SM_RED   (SM_MBAR + 128)            // 4 x 64 floats = 1KB
#define SM_TOTAL (SM_RED + 1024)            // 115840 B; x2 = 231680 <= 228KB/SM

__device__ __forceinline__ uint32_t smem_u32(const void* p) {
    uint32_t a;
    asm("{ .reg .u64 t; cvta.to.shared.u64 t, %1; cvt.u32.u64 %0, t; }" : "=r"(a) : "l"(p));
    return a;
}
__device__ __forceinline__ void ldsm4(uint32_t r[4], uint32_t addr) {
    asm volatile("ldmatrix.sync.aligned.m8n8.x4.shared.b16 {%0,%1,%2,%3}, [%4];"
                 : "=r"(r[0]), "=r"(r[1]), "=r"(r[2]), "=r"(r[3]) : "r"(addr));
}
__device__ __forceinline__ void mma_fp16(float d[4], const uint32_t a[4],
                                         uint32_t b0, uint32_t b1) {
    asm volatile(
        "mma.sync.aligned.m16n8k16.row.col.f32.f16.f16.f32 "
        "{%0,%1,%2,%3}, {%4,%5,%6,%7}, {%8,%9}, {%0,%1,%2,%3};"
        : "+f"(d[0]), "+f"(d[1]), "+f"(d[2]), "+f"(d[3])
        : "r"(a[0]), "r"(a[1]), "r"(a[2]), "r"(a[3]), "r"(b0), "r"(b1));
}
__device__ __forceinline__ void mbar_init(uint32_t m, uint32_t cnt) {
    asm volatile("mbarrier.init.shared.b64 [%0], %1;" :: "r"(m), "r"(cnt) : "memory");
}
__device__ __forceinline__ void mbar_arrive(uint32_t m) {
    asm volatile("mbarrier.arrive.shared.b64 _, [%0];" :: "r"(m) : "memory");
}
__device__ __forceinline__ void mbar_expect_tx(uint32_t m, uint32_t bytes) {
    asm volatile("mbarrier.arrive.expect_tx.shared.b64 _, [%0], %1;"
                 :: "r"(m), "r"(bytes) : "memory");
}
__device__ __forceinline__ void mbar_wait(uint32_t m, uint32_t ph) {
    asm volatile(
        "{\n\t.reg .pred P1;\n\t"
        "WL_%=:\n\t"
        "mbarrier.try_wait.parity.acquire.cta.shared::cta.b64 P1, [%0], %1, 0x989680;\n\t"
        "@P1 bra.uni WD_%=;\n\t"
        "bra.uni WL_%=;\n\t"
        "WD_%=:\n\t}"
        :: "r"(m), "r"(ph) : "memory");
}
__device__ __forceinline__ void bulk_g2s(uint32_t dst, const void* src,
                                         uint32_t bytes, uint32_t mbar) {
    asm volatile(
        "cp.async.bulk.shared::cluster.global.mbarrier::complete_tx::bytes "
        "[%0], [%1], %2, [%3];"
        :: "r"(dst), "l"(src), "r"(bytes), "r"(mbar) : "memory");
}

// ---- prep: bake swizzled B tiles in triangular-walk order ----
__global__ void prep_tiles_kernel(const float* __restrict__ Q) {
    int i = blockIdx.x * blockDim.x + threadIdx.x;   // 0 .. NIT*8192-1
    int t = i >> 13;            // tile index
    int r = (i >> 6) & 127;     // n-row within tile (g - n*128)
    int j = i & 63;             // k-col within tile (f - c*64)
    int n = TN[t], c = TC[t];
    float v = Q[(size_t)(c * KC + j) * F_DIM + n * BN + r];
    uint32_t off = (uint32_t)(r * 128) + (((uint32_t)(j * 2)) ^ ((r & 7) * 16));
    g_Btiles[t * 8192 + (off >> 1)] = __float2half(v);
}

// ---- main kernel ----
__global__ __launch_bounds__(NTHREADS, 2)
void bilinear_fp16_kernel(const float* __restrict__ x, float* __restrict__ out) {
    extern __shared__ __align__(1024) char smem[];
    const uint32_t sbase = smem_u32(smem);
    const int tid  = threadIdx.x;
    const int lane = tid & 31;
    const int wid  = tid >> 5;
    const int wk   = wid & 1;         // k-step half within each chunk
    const int wm   = (wid >> 1) & 1;  // 32-row strip
    const int wn   = wid >> 2;        // 64-col half
    const int r0   = blockIdx.x * BM;

    // ---- init mbarriers + pre-issue first NSTAGE bulk tiles (tid 0) ----
    if (tid == 0) {
        #pragma unroll
        for (int s = 0; s < NSTAGE; ++s) {
            mbar_init(sbase + SM_MBAR + s * 16, 1);       // full
            mbar_init(sbase + SM_MBAR + s * 16 + 8, 8);   // empty (8 warps)
        }
        asm volatile("fence.proxy.async.shared::cta;" ::: "memory");
        #pragma unroll
        for (int s = 0; s < NSTAGE; ++s) {
            uint32_t full = sbase + SM_MBAR + s * 16;
            mbar_expect_tx(full, TILE_B);
            bulk_g2s(sbase + SM_B + s * TILE_B, g_Btiles + s * 8192, TILE_B, full);
        }
    }

    // ---- convert X row-block [64 x 512] fp32 -> fp16 into A ----
    #pragma unroll
    for (int it = 0; it < 16; ++it) {
        int v   = it * NTHREADS + tid;
        int row = v >> 6;                 // 0..63
        int k   = (v & 63) * 8;           // 0..504
        const float* xp = &x[(size_t)(r0 + row) * F_DIM + k];
        float4 t0 = *reinterpret_cast<const float4*>(xp);
        float4 t1 = *reinterpret_cast<const float4*>(xp + 4);
        union { __half2 h[4]; uint4 u; } cvt;
        cvt.h[0] = __floats2half2_rn(t0.x, t0.y);
        cvt.h[1] = __floats2half2_rn(t0.z, t0.w);
        cvt.h[2] = __floats2half2_rn(t1.x, t1.y);
        cvt.h[3] = __floats2half2_rn(t1.z, t1.w);
        uint32_t off = row * 1024 + (((uint32_t)k * 2) ^ ((row & 7) * 16));
        *reinterpret_cast<uint4*>(smem + SM_A + off) = cvt.u;
    }
    __syncthreads();   // A visible; mbarrier inits visible

    // ---- ldmatrix address components ----
    const uint32_t lane_swz = (lane & 7) * 16;
    uint32_t a_base[2];
    #pragma unroll
    for (int j = 0; j < 2; ++j)
        a_base[j] = sbase + SM_A + (wm * 32 + j * 16 + (lane & 15)) * 1024;
    const uint32_t a_seg = (lane >> 4) * 16;

    uint32_t b_base[4];
    #pragma unroll
    for (int X = 0; X < 4; ++X)
        b_base[X] = (uint32_t)((wn * 64 + X * 16 + (lane & 15)) * 128);
    const uint32_t b_seg = (lane >> 4) * 16;

    float d[2][8][4];
    #pragma unroll
    for (int mf = 0; mf < 2; ++mf)
        #pragma unroll
        for (int nj = 0; nj < 8; ++nj)
            #pragma unroll
            for (int q = 0; q < 4; ++q) d[mf][nj][q] = 0.f;

    float acc[2][2];
    acc[0][0] = acc[0][1] = acc[1][0] = acc[1][1] = 0.f;

    const int ep_r  = lane >> 2;
    const int ep_c2 = (lane & 3) * 2;

    int n = 0, c = 0;
    int s = 0, k = 0;        // stage, use-index (R9-proven rolling update)
    for (int it = 0; it < NIT; ++it) {
        const int cmax = 2 * n + 1;
        const int nn = (c < cmax) ? n : n + 1;
        const int cc = (c < cmax) ? c + 1 : 0;

        const uint32_t full  = sbase + SM_MBAR + s * 16;
        const uint32_t empty = full + 8;

        mbar_wait(full, (uint32_t)(k & 1));

        const uint32_t bst = sbase + SM_B + (uint32_t)(s * TILE_B);
        #pragma unroll
        for (int kk2 = 0; kk2 < 2; ++kk2) {
            const int kk = wk * 2 + kk2;
            const uint32_t akb = (uint32_t)(c * 128 + kk * 32) + a_seg;
            uint32_t a[2][4];
            #pragma unroll
            for (int j = 0; j < 2; ++j)
                ldsm4(a[j], a_base[j] + (akb ^ lane_swz));

            const uint32_t bkb = (uint32_t)(kk * 32) + b_seg;
            #pragma unroll
            for (int X = 0; X < 4; ++X) {
                uint32_t b[4];
                ldsm4(b, bst + b_base[X] + (bkb ^ lane_swz));
                #pragma unroll
                for (int mf = 0; mf < 2; ++mf) {
                    mma_fp16(d[mf][X * 2 + 0], a[mf], b[0], b[2]);
                    mma_fp16(d[mf][X * 2 + 1], a[mf], b[1], b[3]);
                }
            }
        }

        // this warp is done reading stage s
        if (lane == 0) mbar_arrive(empty);

        // producer: refill this stage with tile it+NSTAGE
        if (tid == 0 && it + NSTAGE < NIT) {
            mbar_wait(empty, (uint32_t)(k & 1));
            mbar_expect_tx(full, TILE_B);
            bulk_g2s(bst, g_Btiles + (it + NSTAGE) * 8192, TILE_B, full);
        }

        // ---- epilogue when this g-tile's k-loop finishes: x from smem ----
        if (c == cmax) {
            #pragma unroll
            for (int mf = 0; mf < 2; ++mf) {
                #pragma unroll
                for (int rg = 0; rg < 2; ++rg) {
                    const int row = wm * 32 + mf * 16 + rg * 8 + ep_r;
                    const uint32_t rbase = (uint32_t)(row * 1024);
                    const uint32_t rswz  = (row & 7) * 16;
                    float sum = 0.f;
                    #pragma unroll
                    for (int nj = 0; nj < 8; ++nj) {
                        const int col = n * BN + wn * 64 + nj * 8 + ep_c2;
                        uint32_t off = rbase + (((uint32_t)col * 2) ^ rswz);
                        __half2 xh = *reinterpret_cast<const __half2*>(
                            smem + SM_A + off);
                        float2 xf = __half22float2(xh);
                        sum += d[mf][nj][rg * 2 + 0] * xf.x +
                               d[mf][nj][rg * 2 + 1] * xf.y;
                        d[mf][nj][rg * 2 + 0] = 0.f;
                        d[mf][nj][rg * 2 + 1] = 0.f;
                    }
                    acc[mf][rg] += sum;
                }
            }
        }
        n = nn; c = cc;
        if (++s == NSTAGE) { s = 0; ++k; }
    }

    // ---- reduce: quad lanes, then across the wk x wn warp groups via smem ----
    #pragma unroll
    for (int mf = 0; mf < 2; ++mf)
        #pragma unroll
        for (int rg = 0; rg < 2; ++rg) {
            acc[mf][rg] += __shfl_xor_sync(0xffffffffu, acc[mf][rg], 1);
            acc[mf][rg] += __shfl_xor_sync(0xffffffffu, acc[mf][rg], 2);
        }

    float* red = reinterpret_cast<float*>(smem + SM_RED);
    if ((lane & 3) == 0) {
        const int grp = wk * 2 + wn;   // 0..3
        #pragma unroll
        for (int mf = 0; mf < 2; ++mf)
            #pragma unroll
            for (int rg = 0; rg < 2; ++rg) {
                const int row = wm * 32 + mf * 16 + rg * 8 + ep_r;
                red[grp * BM + row] = acc[mf][rg];
            }
    }
    __syncthreads();
    if (tid < BM)
        out[r0 + tid] = red[tid] + red[BM + tid] +
                        red[2 * BM + tid] + red[3 * BM + tid];
}

extern "C" void kernel_launch(void* const* d_in, const int* in_sizes, int n_in,
                              void* d_out, int out_size) {
    const float* x = (const float*)d_in[0];
    const float* Q = (const float*)d_in[1];
    float* out     = (float*)d_out;

    const int B = in_sizes[0] / F_DIM;

    cudaFuncSetAttribute(bilinear_fp16_kernel,
                         cudaFuncAttributeMaxDynamicSharedMemorySize, SM_TOTAL);

    prep_tiles_kernel<<<(NIT * 8192) / 256, 256>>>(Q);
    bilinear_fp16_kernel<<<B / BM, NTHREADS, SM_TOTAL>>>(x, out);
}

// round 13
// speedup vs baseline: 1.2389x; 1.2389x over previous
#include <cuda_runtime.h>
#include <cuda_fp16.h>
#include <cstdint>

// out[b] = x_b^T Q x_b, B=131072, F=512, fp32, Q upper-triangular (incl diag).
// fp16 HMMA. CTA tile 128x128, 512 threads, 16 warps = wk(2) x wm(4) x wn(2),
// warp tile 32x64 over half the k-steps. Pre-baked swizzled B tiles streamed
// via cp.async.bulk into a 4-stage mbarrier ring. X tile converted lazily:
// chunks 0-1 in the prologue, chunk c during iteration c-2 (first use is
// >= NSTAGE iterations later, so readiness rides the ring's release/acquire
// chain). Diagonal half-chunks skip the all-zero wn=0 MMAs. 1 CTA/SM.

#define F_DIM 512
#define BM 128
#define BN 128
#define KC 64
#define NTHREADS 512
#define NIT 20
#define NSTAGE 4
#define TILE_B 16384      // bytes per B tile (128 rows x 128B)

// pre-baked B tiles: [NIT][128 rows][64 halfs], ldmatrix-swizzled
__device__ __half g_Btiles[NIT * 8192];

__device__ __constant__ int TN[NIT] = {0,0,1,1,1,1,2,2,2,2,2,2,3,3,3,3,3,3,3,3};
__device__ __constant__ int TC[NIT] = {0,1,0,1,2,3,0,1,2,3,4,5,0,1,2,3,4,5,6,7};

// smem layout
#define SM_A     0                          // 128 rows x 1024B = 128KB
#define SM_B     131072                     // 4 stages x 16KB = 64KB
#define SM_MBAR  (SM_B + NSTAGE * TILE_B)
#define SM_RED   (SM_MBAR + 128)            // 4 x 128 floats = 2KB
#define SM_TOTAL (SM_RED + 2048)            // 198,784 B; 1 CTA/SM

__device__ __forceinline__ uint32_t smem_u32(const void* p) {
    uint32_t a;
    asm("{ .reg .u64 t; cvta.to.shared.u64 t, %1; cvt.u32.u64 %0, t; }" : "=r"(a) : "l"(p));
    return a;
}
__device__ __forceinline__ void ldsm4(uint32_t r[4], uint32_t addr) {
    asm volatile("ldmatrix.sync.aligned.m8n8.x4.shared.b16 {%0,%1,%2,%3}, [%4];"
                 : "=r"(r[0]), "=r"(r[1]), "=r"(r[2]), "=r"(r[3]) : "r"(addr));
}
__device__ __forceinline__ void mma_fp16(float d[4], const uint32_t a[4],
                                         uint32_t b0, uint32_t b1) {
    asm volatile(
        "mma.sync.aligned.m16n8k16.row.col.f32.f16.f16.f32 "
        "{%0,%1,%2,%3}, {%4,%5,%6,%7}, {%8,%9}, {%0,%1,%2,%3};"
        : "+f"(d[0]), "+f"(d[1]), "+f"(d[2]), "+f"(d[3])
        : "r"(a[0]), "r"(a[1]), "r"(a[2]), "r"(a[3]), "r"(b0), "r"(b1));
}
__device__ __forceinline__ void mbar_init(uint32_t m, uint32_t cnt) {
    asm volatile("mbarrier.init.shared.b64 [%0], %1;" :: "r"(m), "r"(cnt) : "memory");
}
__device__ __forceinline__ void mbar_arrive(uint32_t m) {
    asm volatile("mbarrier.arrive.shared.b64 _, [%0];" :: "r"(m) : "memory");
}
__device__ __forceinline__ void mbar_expect_tx(uint32_t m, uint32_t bytes) {
    asm volatile("mbarrier.arrive.expect_tx.shared.b64 _, [%0], %1;"
                 :: "r"(m), "r"(bytes) : "memory");
}
__device__ __forceinline__ void mbar_wait(uint32_t m, uint32_t ph) {
    asm volatile(
        "{\n\t.reg .pred P1;\n\t"
        "WL_%=:\n\t"
        "mbarrier.try_wait.parity.acquire.cta.shared::cta.b64 P1, [%0], %1, 0x989680;\n\t"
        "@P1 bra.uni WD_%=;\n\t"
        "bra.uni WL_%=;\n\t"
        "WD_%=:\n\t}"
        :: "r"(m), "r"(ph) : "memory");
}
__device__ __forceinline__ void bulk_g2s(uint32_t dst, const void* src,
                                         uint32_t bytes, uint32_t mbar) {
    asm volatile(
        "cp.async.bulk.shared::cluster.global.mbarrier::complete_tx::bytes "
        "[%0], [%1], %2, [%3];"
        :: "r"(dst), "l"(src), "r"(bytes), "r"(mbar) : "memory");
}

// ---- prep: bake swizzled B tiles in triangular-walk order ----
__global__ void prep_tiles_kernel(const float* __restrict__ Q) {
    int i = blockIdx.x * blockDim.x + threadIdx.x;   // 0 .. NIT*8192-1
    int t = i >> 13;            // tile index
    int r = (i >> 6) & 127;     // n-row within tile (g - n*128)
    int j = i & 63;             // k-col within tile (f - c*64)
    int n = TN[t], c = TC[t];
    float v = Q[(size_t)(c * KC + j) * F_DIM + n * BN + r];
    uint32_t off = (uint32_t)(r * 128) + (((uint32_t)(j * 2)) ^ ((r & 7) * 16));
    g_Btiles[t * 8192 + (off >> 1)] = __float2half(v);
}

// convert one 8-float granule of x into the swizzled A tile
__device__ __forceinline__ void cvt_granule(const float* __restrict__ x,
                                            char* smem, int r0, int row, int k) {
    const float* xp = &x[(size_t)(r0 + row) * F_DIM + k];
    float4 t0 = *reinterpret_cast<const float4*>(xp);
    float4 t1 = *reinterpret_cast<const float4*>(xp + 4);
    union { __half2 h[4]; uint4 u; } cvt;
    cvt.h[0] = __floats2half2_rn(t0.x, t0.y);
    cvt.h[1] = __floats2half2_rn(t0.z, t0.w);
    cvt.h[2] = __floats2half2_rn(t1.x, t1.y);
    cvt.h[3] = __floats2half2_rn(t1.z, t1.w);
    uint32_t off = row * 1024 + (((uint32_t)k * 2) ^ ((row & 7) * 16));
    *reinterpret_cast<uint4*>(smem + SM_A + off) = cvt.u;
}

// ---- main kernel ----
__global__ __launch_bounds__(NTHREADS, 1)
void bilinear_fp16_kernel(const float* __restrict__ x, float* __restrict__ out) {
    extern __shared__ __align__(1024) char smem[];
    const uint32_t sbase = smem_u32(smem);
    const int tid  = threadIdx.x;
    const int lane = tid & 31;
    const int wid  = tid >> 5;
    const int wk   = wid & 1;         // k-step half within each chunk
    const int wm   = (wid >> 1) & 3;  // 32-row strip
    const int wn   = wid >> 3;        // 64-col half
    const int r0   = blockIdx.x * BM;

    // ---- init mbarriers + pre-issue first NSTAGE bulk tiles (tid 0) ----
    if (tid == 0) {
        #pragma unroll
        for (int s = 0; s < NSTAGE; ++s) {
            mbar_init(sbase + SM_MBAR + s * 16, 1);        // full
            mbar_init(sbase + SM_MBAR + s * 16 + 8, 16);   // empty (16 warps)
        }
        asm volatile("fence.proxy.async.shared::cta;" ::: "memory");
        #pragma unroll
        for (int s = 0; s < NSTAGE; ++s) {
            uint32_t full = sbase + SM_MBAR + s * 16;
            mbar_expect_tx(full, TILE_B);
            bulk_g2s(sbase + SM_B + s * TILE_B, g_Btiles + s * 8192, TILE_B, full);
        }
    }

    // ---- prologue: convert only chunks 0-1 of X (cols 0..127) ----
    #pragma unroll
    for (int it2 = 0; it2 < 4; ++it2) {
        int v   = it2 * NTHREADS + tid;   // 0..2047
        int row = v >> 4;                 // 0..127
        int k   = (v & 15) * 8;           // 0..120
        cvt_granule(x, smem, r0, row, k);
    }
    __syncthreads();   // chunks 0-1 visible; mbarrier inits visible

    // ---- ldmatrix address components ----
    const uint32_t lane_swz = (lane & 7) * 16;
    uint32_t a_base[2];
    #pragma unroll
    for (int j = 0; j < 2; ++j)
        a_base[j] = sbase + SM_A + (wm * 32 + j * 16 + (lane & 15)) * 1024;
    const uint32_t a_seg = (lane >> 4) * 16;

    uint32_t b_base[4];
    #pragma unroll
    for (int X = 0; X < 4; ++X)
        b_base[X] = (uint32_t)((wn * 64 + X * 16 + (lane & 15)) * 128);
    const uint32_t b_seg = (lane >> 4) * 16;

    float d[2][8][4];
    #pragma unroll
    for (int mf = 0; mf < 2; ++mf)
        #pragma unroll
        for (int nj = 0; nj < 8; ++nj)
            #pragma unroll
            for (int q = 0; q < 4; ++q) d[mf][nj][q] = 0.f;

    float acc[2][2];
    acc[0][0] = acc[0][1] = acc[1][0] = acc[1][1] = 0.f;

    const int ep_r  = lane >> 2;
    const int ep_c2 = (lane & 3) * 2;

    int n = 0, c = 0;
    int s = 0, k = 0;        // stage, use-index
    for (int it = 0; it < NIT; ++it) {
        const int cmax = 2 * n + 1;
        const int nn = (c < cmax) ? n : n + 1;
        const int cc = (c < cmax) ? c + 1 : 0;

        // ---- lazy A conversion: chunk it+2 during iterations 0..5.
        // First use of chunk c is >= NSTAGE iterations after conversion, so
        // visibility rides the ring's release/acquire chain.
        if (it < 6) {
            const int ch = it + 2;
            #pragma unroll
            for (int j = 0; j < 2; ++j) {
                int v   = j * NTHREADS + tid;   // 0..1023
                int row = v >> 3;               // 0..127
                int kq  = ch * KC + (v & 7) * 8;
                cvt_granule(x, smem, r0, row, kq);
            }
        }

        const uint32_t full  = sbase + SM_MBAR + s * 16;
        const uint32_t empty = full + 8;

        // wn=0 columns of the second diagonal half-chunk are all zero: skip.
        const bool skipB = (c == cmax) && (wn == 0);

        if (!skipB) {
            mbar_wait(full, (uint32_t)(k & 1));

            const uint32_t bst = sbase + SM_B + (uint32_t)(s * TILE_B);
            #pragma unroll
            for (int kk2 = 0; kk2 < 2; ++kk2) {
                const int kk = wk * 2 + kk2;
                const uint32_t akb = (uint32_t)(c * 128 + kk * 32) + a_seg;
                uint32_t a[2][4];
                #pragma unroll
                for (int j = 0; j < 2; ++j)
                    ldsm4(a[j], a_base[j] + (akb ^ lane_swz));

                const uint32_t bkb = (uint32_t)(kk * 32) + b_seg;
                #pragma unroll
                for (int X = 0; X < 4; ++X) {
                    uint32_t b[4];
                    ldsm4(b, bst + b_base[X] + (bkb ^ lane_swz));
                    #pragma unroll
                    for (int mf = 0; mf < 2; ++mf) {
                        mma_fp16(d[mf][X * 2 + 0], a[mf], b[0], b[2]);
                        mma_fp16(d[mf][X * 2 + 1], a[mf], b[1], b[3]);
                    }
                }
            }
        }

        // publish this warp's conversion STS + release stage read
        __syncwarp();
        if (lane == 0) mbar_arrive(empty);

        // producer: refill this stage with tile it+NSTAGE
        if (tid == 0 && it + NSTAGE < NIT) {
            mbar_wait(empty, (uint32_t)(k & 1));
            mbar_expect_tx(full, TILE_B);
            bulk_g2s(sbase + SM_B + (uint32_t)(s * TILE_B),
                     g_Btiles + (it + NSTAGE) * 8192, TILE_B, full);
        }

        // ---- epilogue when this g-tile's k-loop finishes: x from smem ----
        if (c == cmax) {
            #pragma unroll
            for (int mf = 0; mf < 2; ++mf) {
                #pragma unroll
                for (int rg = 0; rg < 2; ++rg) {
                    const int row = wm * 32 + mf * 16 + rg * 8 + ep_r;
                    const uint32_t rbase = (uint32_t)(row * 1024);
                    const uint32_t rswz  = (row & 7) * 16;
                    float sum = 0.f;
                    #pragma unroll
                    for (int nj = 0; nj < 8; ++nj) {
                        const int col = n * BN + wn * 64 + nj * 8 + ep_c2;
                        uint32_t off = rbase + (((uint32_t)col * 2) ^ rswz);
                        __half2 xh = *reinterpret_cast<const __half2*>(
                            smem + SM_A + off);
                        float2 xf = __half22float2(xh);
                        sum += d[mf][nj][rg * 2 + 0] * xf.x +
                               d[mf][nj][rg * 2 + 1] * xf.y;
                        d[mf][nj][rg * 2 + 0] = 0.f;
                        d[mf][nj][rg * 2 + 1] = 0.f;
                    }
                    acc[mf][rg] += sum;
                }
            }
        }
        n = nn; c = cc;
        if (++s == NSTAGE) { s = 0; ++k; }
    }

    // ---- reduce: quad lanes, then across the wk x wn warp groups via smem ----
    #pragma unroll
    for (int mf = 0; mf < 2; ++mf)
        #pragma unroll
        for (int rg = 0; rg < 2; ++rg) {
            acc[mf][rg] += __shfl_xor_sync(0xffffffffu, acc[mf][rg], 1);
            acc[mf][rg] += __shfl_xor_sync(0xffffffffu, acc[mf][rg], 2);
        }

    float* red = reinterpret_cast<float*>(smem + SM_RED);
    if ((lane & 3) == 0) {
        const int grp = wk * 2 + wn;   // 0..3
        #pragma unroll
        for (int mf = 0; mf < 2; ++mf)
            #pragma unroll
            for (int rg = 0; rg < 2; ++rg) {
                const int row = wm * 32 + mf * 16 + rg * 8 + ep_r;
                red[grp * BM + row] = acc[mf][rg];
            }
    }
    __syncthreads();
    if (tid < BM)
        out[r0 + tid] = red[tid] + red[BM + tid] +
                        red[2 * BM + tid] + red[3 * BM + tid];
}

extern "C" void kernel_launch(void* const* d_in, const int* in_sizes, int n_in,
                              void* d_out, int out_size) {
    const float* x = (const float*)d_in[0];
    const float* Q = (const float*)d_in[1];
    float* out     = (float*)d_out;

    const int B = in_sizes[0] / F_DIM;

    cudaFuncSetAttribute(bilinear_fp16_kernel,
                         cudaFuncAttributeMaxDynamicSharedMemorySize, SM_TOTAL);

    prep_tiles_kernel<<<(NIT * 8192) / 256, 256>>>(Q);
    bilinear_fp16_kernel<<<B / BM, NTHREADS, SM_TOTAL>>>(x, out);
}

// round 14
// speedup vs baseline: 1.4649x; 1.1823x over previous
#include <cuda_runtime.h>
#include <cuda_fp16.h>
#include <cstdint>

// out[b] = x_b^T Q x_b, B=131072, F=512, fp32, Q upper-triangular (incl diag).
// fp16 HMMA. CTA tile 64x128, 256 threads, 8 warps = wk(2) x wm(2) x wn(2),
// warp tile 32x64 over half the k-steps. B is pre-baked into mma REGISTER
// FRAGMENT layout (uint4 per lane per 16x16 frag) and fetched with coalesced
// __ldg from the L2-hot 320KB array => NO smem B, NO mbarriers, NO main-loop
// synchronization of any kind. Triangular walk fully unrolled (compile-time
// n,c). Diagonal half-chunks skip the all-zero wn=0 MMAs. 66.5KB smem =>
// 2 CTAs/SM; co-resident CTAs hide each other's prologue/epilogue.

#define F_DIM 512
#define BM 64
#define BN 128
#define KC 64
#define NTHREADS 256
#define NIT 20

// B fragments: [tile t][frag fidx=(kk*2+wn)*4+X][lane] -> uint4 {b0,b1,b2,b3}
__device__ uint4 g_Bfrag[NIT * 32 * 32];   // 320KB, L2-resident

__device__ __constant__ int TN[NIT] = {0,0,1,1,1,1,2,2,2,2,2,2,3,3,3,3,3,3,3,3};
__device__ __constant__ int TC[NIT] = {0,1,0,1,2,3,0,1,2,3,4,5,0,1,2,3,4,5,6,7};

// smem layout
#define SM_A     0                 // 64 rows x 1024B = 64KB
#define SM_RED   65536             // 4 x 64 floats = 1KB
#define SM_TOTAL 66560             // x2 CTAs = 133KB < SM limit

__device__ __forceinline__ uint32_t smem_u32(const void* p) {
    uint32_t a;
    asm("{ .reg .u64 t; cvta.to.shared.u64 t, %1; cvt.u32.u64 %0, t; }" : "=r"(a) : "l"(p));
    return a;
}
__device__ __forceinline__ void ldsm4(uint32_t r[4], uint32_t addr) {
    asm volatile("ldmatrix.sync.aligned.m8n8.x4.shared.b16 {%0,%1,%2,%3}, [%4];"
                 : "=r"(r[0]), "=r"(r[1]), "=r"(r[2]), "=r"(r[3]) : "r"(addr));
}
__device__ __forceinline__ void mma_fp16(float d[4], const uint32_t a[4],
                                         uint32_t b0, uint32_t b1) {
    asm volatile(
        "mma.sync.aligned.m16n8k16.row.col.f32.f16.f16.f32 "
        "{%0,%1,%2,%3}, {%4,%5,%6,%7}, {%8,%9}, {%0,%1,%2,%3};"
        : "+f"(d[0]), "+f"(d[1]), "+f"(d[2]), "+f"(d[3])
        : "r"(a[0]), "r"(a[1]), "r"(a[2]), "r"(a[3]), "r"(b0), "r"(b1));
}
__device__ __forceinline__ uint32_t packh2(float lo, float hi) {
    union { __half2 h; uint32_t u; } cvt;
    cvt.h = __floats2half2_rn(lo, hi);
    return cvt.u;
}

// ---- prep: bake B fragments in mma register layout ----
// m16n8k16 .col B frag (per 16x16 ldsm.x4 block): lane l holds
//   b0 = Bt[n0  ][k0], Bt[n0  ][k0+1]     (n0 = X*16 + wn*64 + (l>>2),
//   b1 = Bt[n0+8][k0], Bt[n0+8][k0+1]      k0 = kk*16 + 2*(l&3))
//   b2 = Bt[n0  ][k0+8], Bt[n0  ][k0+9]
//   b3 = Bt[n0+8][k0+8], Bt[n0+8][k0+9]
// where Bt[r][j] = Q[c*64+j][n*128+r]  (tile (n,c) of Q^T).
__global__ void prep_frags_kernel(const float* __restrict__ Q) {
    int i = blockIdx.x * blockDim.x + threadIdx.x;   // 0 .. NIT*1024-1
    int t    = i >> 10;
    int fidx = (i >> 5) & 31;
    int l    = i & 31;
    int kk = fidx >> 3, wn = (fidx >> 2) & 1, X = fidx & 3;
    int n = TN[t], c = TC[t];
    int n0 = wn * 64 + X * 16 + (l >> 2);
    int k0 = kk * 16 + 2 * (l & 3);
    const float* Qb = Q + (size_t)(c * KC) * F_DIM + n * BN;   // + k*512 + r
    #define QV(dk, dg) Qb[(size_t)(k0 + (dk)) * F_DIM + n0 + (dg)]
    uint4 v;
    v.x = packh2(QV(0, 0), QV(1, 0));
    v.y = packh2(QV(0, 8), QV(1, 8));
    v.z = packh2(QV(8, 0), QV(9, 0));
    v.w = packh2(QV(8, 8), QV(9, 8));
    #undef QV
    g_Bfrag[(t * 32 + fidx) * 32 + l] = v;
}

// ---- main kernel ----
__global__ __launch_bounds__(NTHREADS, 2)
void bilinear_fp16_kernel(const float* __restrict__ x, float* __restrict__ out) {
    extern __shared__ __align__(1024) char smem[];
    const uint32_t sbase = smem_u32(smem);
    const int tid  = threadIdx.x;
    const int lane = tid & 31;
    const int wid  = tid >> 5;
    const int wk   = wid & 1;         // k-step half within each chunk
    const int wm   = (wid >> 1) & 1;  // 32-row strip
    const int wn   = wid >> 2;        // 64-col half
    const int r0   = blockIdx.x * BM;

    // ---- prologue: convert full X row-block [64 x 512] fp32 -> fp16 into A ----
    #pragma unroll
    for (int it = 0; it < 16; ++it) {
        int v   = it * NTHREADS + tid;
        int row = v >> 6;                 // 0..63
        int k   = (v & 63) * 8;           // 0..504
        const float* xp = &x[(size_t)(r0 + row) * F_DIM + k];
        float4 t0 = *reinterpret_cast<const float4*>(xp);
        float4 t1 = *reinterpret_cast<const float4*>(xp + 4);
        uint4 u;
        u.x = packh2(t0.x, t0.y);
        u.y = packh2(t0.z, t0.w);
        u.z = packh2(t1.x, t1.y);
        u.w = packh2(t1.z, t1.w);
        uint32_t off = row * 1024 + (((uint32_t)k * 2) ^ ((row & 7) * 16));
        *reinterpret_cast<uint4*>(smem + SM_A + off) = u;
    }
    __syncthreads();   // the ONLY main-path synchronization

    // ---- ldmatrix address components for A ----
    const uint32_t lane_swz = (lane & 7) * 16;
    uint32_t a_base[2];
    #pragma unroll
    for (int j = 0; j < 2; ++j)
        a_base[j] = sbase + SM_A + (wm * 32 + j * 16 + (lane & 15)) * 1024;
    const uint32_t a_seg = (lane >> 4) * 16;

    // B fragment base pointer for this warp's (wn, lane)
    const uint4* bf = g_Bfrag + wn * 4 * 32 + lane;   // + (t*32 + kk*8 + X)*32

    float d[2][8][4];
    #pragma unroll
    for (int mf = 0; mf < 2; ++mf)
        #pragma unroll
        for (int nj = 0; nj < 8; ++nj)
            #pragma unroll
            for (int q = 0; q < 4; ++q) d[mf][nj][q] = 0.f;

    float acc[2][2];
    acc[0][0] = acc[0][1] = acc[1][0] = acc[1][1] = 0.f;

    const int ep_r  = lane >> 2;
    const int ep_c2 = (lane & 3) * 2;

    int t = 0;   // tile index in triangular-walk order
    #pragma unroll
    for (int n = 0; n < 4; ++n) {
        #pragma unroll
        for (int c = 0; c <= 2 * n + 1; ++c, ++t) {
            const bool lastc = (c == 2 * n + 1);

            // wn=0 columns of the second diagonal half-chunk are zero: skip
            if (!(lastc && wn == 0)) {
                #pragma unroll
                for (int kk2 = 0; kk2 < 2; ++kk2) {
                    const int kk = wk * 2 + kk2;
                    const uint32_t akb = (uint32_t)(c * 128 + kk * 32) + a_seg;
                    uint32_t a[2][4];
                    #pragma unroll
                    for (int j = 0; j < 2; ++j)
                        ldsm4(a[j], a_base[j] + (akb ^ lane_swz));

                    #pragma unroll
                    for (int X = 0; X < 4; ++X) {
                        uint4 bv = __ldg(bf + (t * 32 + kk * 8 + X) * 32);
                        mma_fp16(d[0][X * 2 + 0], a[0], bv.x, bv.z);
                        mma_fp16(d[0][X * 2 + 1], a[0], bv.y, bv.w);
                        mma_fp16(d[1][X * 2 + 0], a[1], bv.x, bv.z);
                        mma_fp16(d[1][X * 2 + 1], a[1], bv.y, bv.w);
                    }
                }
            }

            // ---- epilogue when this g-tile's k-loop finishes: x from smem ----
            if (lastc) {
                #pragma unroll
                for (int mf = 0; mf < 2; ++mf) {
                    #pragma unroll
                    for (int rg = 0; rg < 2; ++rg) {
                        const int row = wm * 32 + mf * 16 + rg * 8 + ep_r;
                        const uint32_t rbase = (uint32_t)(row * 1024);
                        const uint32_t rswz  = (row & 7) * 16;
                        float sum = 0.f;
                        #pragma unroll
                        for (int nj = 0; nj < 8; ++nj) {
                            const int col = n * BN + wn * 64 + nj * 8 + ep_c2;
                            uint32_t off = rbase + (((uint32_t)col * 2) ^ rswz);
                            __half2 xh = *reinterpret_cast<const __half2*>(
                                smem + SM_A + off);
                            float2 xf = __half22float2(xh);
                            sum += d[mf][nj][rg * 2 + 0] * xf.x +
                                   d[mf][nj][rg * 2 + 1] * xf.y;
                            d[mf][nj][rg * 2 + 0] = 0.f;
                            d[mf][nj][rg * 2 + 1] = 0.f;
                        }
                        acc[mf][rg] += sum;
                    }
                }
            }
        }
    }

    // ---- reduce: quad lanes, then across the wk x wn warp groups via smem ----
    #pragma unroll
    for (int mf = 0; mf < 2; ++mf)
        #pragma unroll
        for (int rg = 0; rg < 2; ++rg) {
            acc[mf][rg] += __shfl_xor_sync(0xffffffffu, acc[mf][rg], 1);
            acc[mf][rg] += __shfl_xor_sync(0xffffffffu, acc[mf][rg], 2);
        }

    float* red = reinterpret_cast<float*>(smem + SM_RED);
    if ((lane & 3) == 0) {
        const int grp = wk * 2 + wn;   // 0..3
        #pragma unroll
        for (int mf = 0; mf < 2; ++mf)
            #pragma unroll
            for (int rg = 0; rg < 2; ++rg) {
                const int row = wm * 32 + mf * 16 + rg * 8 + ep_r;
                red[grp * BM + row] = acc[mf][rg];
            }
    }
    __syncthreads();
    if (tid < BM)
        out[r0 + tid] = red[tid] + red[BM + tid] +
                        red[2 * BM + tid] + red[3 * BM + tid];
}

extern "C" void kernel_launch(void* const* d_in, const int* in_sizes, int n_in,
                              void* d_out, int out_size) {
    const float* x = (const float*)d_in[0];
    const float* Q = (const float*)d_in[1];
    float* out     = (float*)d_out;

    const int B = in_sizes[0] / F_DIM;

    cudaFuncSetAttribute(bilinear_fp16_kernel,
                         cudaFuncAttributeMaxDynamicSharedMemorySize, SM_TOTAL);

    prep_frags_kernel<<<(NIT * 1024) / 256, 256>>>(Q);
    bilinear_fp16_kernel<<<B / BM, NTHREADS, SM_TOTAL>>>(x, out);
}